// round 3
// baseline (speedup 1.0000x reference)
#include <cuda_runtime.h>
#include <cstdint>

#define HID 128
#define NB 50000
#define NC 2500
#define NLAYERS 2
#define NBF (NB*HID)
#define NCF (NC*HID)

#define BSTR 136                      // bf16 elements per smem row (128 + 8 pad)
#define TILE_BYTES (128*BSTR*2)       // 34816 B per bf16 tile
#define SOFF_AH 0
#define SOFF_AL (1*TILE_BYTES)
#define SOFF_BH (2*TILE_BYTES)
#define SOFF_BL (3*TILE_BYTES)
#define SMEM_TOTAL (4*TILE_BYTES)     // 139264 B -> 1 CTA/SM
#define CSTR 132                      // f32 epilogue tile stride

// ---------------- helpers ----------------
__device__ __forceinline__ uint32_t smem_u32(const void* p){
    uint32_t a; asm("{ .reg .u64 t; cvta.to.shared.u64 t, %1; cvt.u32.u64 %0, t; }" : "=r"(a) : "l"(p));
    return a;
}
__device__ __forceinline__ float gelu_f(float x){
    return 0.5f * x * (1.0f + erff(x * 0.70710678118654752440f));
}
__device__ __forceinline__ void red_add_v4(float* p, float a, float b, float c, float d){
    asm volatile("red.global.add.v4.f32 [%0], {%1, %2, %3, %4};"
                 :: "l"(p), "f"(a), "f"(b), "f"(c), "f"(d) : "memory");
}
// split (x,y) into packed bf16x2 hi (truncation) and lo (round-to-nearest of residual)
__device__ __forceinline__ void split2(float x, float y, uint32_t& hi, uint32_t& lo){
    uint32_t ux = __float_as_uint(x), uy = __float_as_uint(y);
    hi = (ux >> 16) | (uy & 0xFFFF0000u);
    float lx = x - __uint_as_float(ux & 0xFFFF0000u);
    float ly = y - __uint_as_float(uy & 0xFFFF0000u);
    asm("cvt.rn.bf16x2.f32 %0, %1, %2;" : "=r"(lo) : "f"(ly), "f"(lx));
}
__device__ __forceinline__ void ldsm_x4(uint32_t* r, uint32_t addr){
    asm volatile("ldmatrix.sync.aligned.m8n8.x4.shared.b16 {%0,%1,%2,%3}, [%4];"
        : "=r"(r[0]), "=r"(r[1]), "=r"(r[2]), "=r"(r[3]) : "r"(addr));
}
__device__ __forceinline__ void ldsm_x2t(uint32_t& r0, uint32_t& r1, uint32_t addr){
    asm volatile("ldmatrix.sync.aligned.m8n8.x2.trans.shared.b16 {%0,%1}, [%2];"
        : "=r"(r0), "=r"(r1) : "r"(addr));
}
__device__ __forceinline__ void mma16816(float* c, const uint32_t* a, uint32_t b0, uint32_t b1){
    asm volatile("mma.sync.aligned.m16n8k16.row.col.f32.bf16.bf16.f32 "
        "{%0,%1,%2,%3}, {%4,%5,%6,%7}, {%8,%9}, {%0,%1,%2,%3};"
        : "+f"(c[0]), "+f"(c[1]), "+f"(c[2]), "+f"(c[3])
        : "r"(a[0]), "r"(a[1]), "r"(a[2]), "r"(a[3]), "r"(b0), "r"(b1));
}

// ------------- fused tile kernel: D = (scale*A) @ W, 3xBF16 split on HMMA -------------
// edge mode (ei!=null): m = gelu(D + bias + XS[src]) * ew -> red.add into OUT[dst]
// linear mode:          OUT[row] = [gelu]( D + bias )
extern "C" __global__ void __launch_bounds__(256, 1)
tile_gemm(const float* __restrict__ A, const float* __restrict__ W,
          const float* __restrict__ bias, const int* __restrict__ ei,
          const float* __restrict__ ew, const float* __restrict__ XS,
          float* __restrict__ OUT, int M, const float* __restrict__ eps_ptr,
          int do_gelu)
{
    extern __shared__ char smem[];
    uint32_t* sm32 = (uint32_t*)smem;
    int t = threadIdx.x;
    int w = t >> 5, l = t & 31;
    const bool edge = (ei != nullptr);
    float scale = eps_ptr ? (1.0f + *eps_ptr) : 1.0f;
    int row0 = blockIdx.x * 128;

    // ---- stage A rows (fp32 -> bf16 hi/lo, scale folded) ----
    {
        int r = t >> 1, half = t & 1;
        int grow = row0 + r;
        bool v = (grow < M);
        const float4* g = (const float4*)(A + (size_t)grow * HID) + half * 16;
        uint32_t* ah = sm32 + (SOFF_AH >> 2) + r * (BSTR >> 1) + half * 32;
        uint32_t* al = sm32 + (SOFF_AL >> 2) + r * (BSTR >> 1) + half * 32;
        #pragma unroll
        for (int i = 0; i < 16; i++){
            float4 x = v ? g[i] : make_float4(0.f, 0.f, 0.f, 0.f);
            x.x *= scale; x.y *= scale; x.z *= scale; x.w *= scale;
            uint32_t h0, l0, h1, l1;
            split2(x.x, x.y, h0, l0); split2(x.z, x.w, h1, l1);
            ah[2*i] = h0; ah[2*i+1] = h1;
            al[2*i] = l0; al[2*i+1] = l1;
        }
    }
    // ---- stage W rows [k][n] (no transpose; ldmatrix.trans provides B frag) ----
    {
        int k = t >> 1, half = t & 1;
        const float4* g = (const float4*)(W + (size_t)k * HID) + half * 16;
        uint32_t* bh = sm32 + (SOFF_BH >> 2) + k * (BSTR >> 1) + half * 32;
        uint32_t* bl = sm32 + (SOFF_BL >> 2) + k * (BSTR >> 1) + half * 32;
        #pragma unroll
        for (int i = 0; i < 16; i++){
            float4 x = g[i];
            uint32_t h0, l0, h1, l1;
            split2(x.x, x.y, h0, l0); split2(x.z, x.w, h1, l1);
            bh[2*i] = h0; bh[2*i+1] = h1;
            bl[2*i] = l0; bl[2*i+1] = l1;
        }
    }
    __syncthreads();

    // ---- HMMA mainloop: warp w owns rows 16w..16w+15, all 128 cols ----
    float acc[16][4];
    #pragma unroll
    for (int n = 0; n < 16; n++){
        acc[n][0] = 0.f; acc[n][1] = 0.f; acc[n][2] = 0.f; acc[n][3] = 0.f;
    }
    uint32_t sbase = smem_u32(smem);
    int arow = 16 * w + (l & 15);
    int akoff = (l >> 4) * 8;
    uint32_t aAh = sbase + SOFF_AH + (uint32_t)(arow * BSTR + akoff) * 2;
    uint32_t aAl = sbase + SOFF_AL + (uint32_t)(arow * BSTR + akoff) * 2;
    uint32_t aBh = sbase + SOFF_BH + (uint32_t)((l & 15) * BSTR) * 2;
    uint32_t aBl = sbase + SOFF_BL + (uint32_t)((l & 15) * BSTR) * 2;

    #pragma unroll 1
    for (int ks = 0; ks < 8; ks++){
        uint32_t ah[4], al[4];
        ldsm_x4(ah, aAh);
        ldsm_x4(al, aAl);
        aAh += 32; aAl += 32;           // k += 16 (bf16 bytes)
        #pragma unroll
        for (int n = 0; n < 16; n++){
            uint32_t bh0, bh1, bl0, bl1;
            ldsm_x2t(bh0, bh1, aBh + n * 16);
            ldsm_x2t(bl0, bl1, aBl + n * 16);
            mma16816(acc[n], ah, bh0, bh1);
            mma16816(acc[n], ah, bl0, bl1);
            mma16816(acc[n], al, bh0, bh1);
        }
        aBh += 16 * BSTR * 2;           // next 16 k-rows
        aBl += 16 * BSTR * 2;
    }

    // ---- accumulators -> smem f32 tile (reuse A region) ----
    __syncthreads();
    float* Cs = (float*)smem;
    {
        int r0 = 16 * w + (l >> 2);
        int cb = 2 * (l & 3);
        #pragma unroll
        for (int n = 0; n < 16; n++){
            int c = 8 * n + cb;
            *(float2*)(Cs + r0 * CSTR + c)       = make_float2(acc[n][0], acc[n][1]);
            *(float2*)(Cs + (r0 + 8) * CSTR + c) = make_float2(acc[n][2], acc[n][3]);
        }
    }
    __syncthreads();

    // ---- fused epilogue: 2 threads per row ----
    {
        int r = t >> 1, half = t & 1;
        int grow = row0 + r;
        if (grow < M){
            int c0 = half * 64;
            if (!edge){
                float4* o4 = (float4*)(OUT + (size_t)grow * HID + c0);
                #pragma unroll
                for (int i = 0; i < 16; i++){
                    int c = c0 + 4 * i;
                    float4 bv = *(const float4*)(bias + c);
                    float o0 = Cs[r * CSTR + c + 0] + bv.x;
                    float o1 = Cs[r * CSTR + c + 1] + bv.y;
                    float o2 = Cs[r * CSTR + c + 2] + bv.z;
                    float o3 = Cs[r * CSTR + c + 3] + bv.w;
                    if (do_gelu){ o0 = gelu_f(o0); o1 = gelu_f(o1); o2 = gelu_f(o2); o3 = gelu_f(o3); }
                    o4[i] = make_float4(o0, o1, o2, o3);
                }
            } else {
                int src = ei[grow], dst = ei[M + grow];
                float wgt = ew[grow];
                const float4* xs4 = (const float4*)(XS + (size_t)src * HID);
                #pragma unroll
                for (int i = 0; i < 16; i++){
                    int c = c0 + 4 * i;
                    float4 bv = *(const float4*)(bias + c);
                    float4 xv = xs4[c >> 2];
                    float m0 = gelu_f(Cs[r * CSTR + c + 0] + bv.x + xv.x) * wgt;
                    float m1 = gelu_f(Cs[r * CSTR + c + 1] + bv.y + xv.y) * wgt;
                    float m2 = gelu_f(Cs[r * CSTR + c + 2] + bv.z + xv.z) * wgt;
                    float m3 = gelu_f(Cs[r * CSTR + c + 3] + bv.w + xv.w) * wgt;
                    red_add_v4(OUT + (size_t)dst * HID + c, m0, m1, m2, m3);
                }
            }
        }
    }
}

// ---------- x += gelu(a + b) ----------
extern "C" __global__ void combine_kernel(float* __restrict__ x, const float* __restrict__ a,
                                          const float* __restrict__ b, int n){
    int i = blockIdx.x * blockDim.x + threadIdx.x;
    if (i < n) x[i] += gelu_f(a[i] + b[i]);
}

// ---------- scratch ----------
__device__ float g_buf[(size_t)5*NBF + (size_t)5*NCF];

extern "C" void kernel_launch(void* const* d_in, const int* in_sizes, int n_in,
                              void* d_out, int out_size)
{
    (void)n_in; (void)out_size;
    const float* x_base = (const float*)d_in[0];
    const float* x_cent = (const float*)d_in[1];
    const int*   ei[4]  = {(const int*)d_in[2], (const int*)d_in[5], (const int*)d_in[8],  (const int*)d_in[11]};
    const float* ea[4]  = {(const float*)d_in[3], (const float*)d_in[6], (const float*)d_in[9],  (const float*)d_in[12]};
    const float* ewt[4] = {(const float*)d_in[4], (const float*)d_in[7], (const float*)d_in[10], (const float*)d_in[13]};
    const float* Wsrc = (const float*)d_in[14];
    const float* bsrc = (const float*)d_in[15];
    const float* Wdst = (const float*)d_in[16];
    const float* bdst = (const float*)d_in[17];
    const float* eps  = (const float*)d_in[18];
    const float* We   = (const float*)d_in[19];
    const float* be   = (const float*)d_in[20];
    const float* Wm1  = (const float*)d_in[21];
    const float* bm1  = (const float*)d_in[22];
    const float* Wm2  = (const float*)d_in[23];
    const float* bm2  = (const float*)d_in[24];

    float* base = nullptr;
    cudaGetSymbolAddress((void**)&base, g_buf);
    float* xb     = base;
    float* xs_bb  = base + (size_t)1*NBF;
    float* xs_bc  = base + (size_t)2*NBF;
    float* agg_bb = base + (size_t)3*NBF;
    float* agg_cb = base + (size_t)4*NBF;
    float* xc     = base + (size_t)5*NBF;
    float* xs_cc  = xc + (size_t)1*NCF;
    float* xs_cb  = xc + (size_t)2*NCF;
    float* agg_bc = xc + (size_t)3*NCF;
    float* agg_cc = xc + (size_t)4*NCF;

    cudaFuncSetAttribute((const void*)tile_gemm, cudaFuncAttributeMaxDynamicSharedMemorySize, SMEM_TOTAL);

    cudaMemcpyAsync(xb, x_base, sizeof(float)*(size_t)NBF, cudaMemcpyDeviceToDevice, 0);
    cudaMemcpyAsync(xc, x_cent, sizeof(float)*(size_t)NCF, cudaMemcpyDeviceToDevice, 0);

    const int GB = (NB + 127) / 128;
    const int GC = (NC + 127) / 128;

    for (int l = 0; l < NLAYERS; l++){
        #define WOFF(P,t) ((P) + ((size_t)l*4 + (t))*HID*HID)
        #define BOFF(P,t) ((P) + ((size_t)l*4 + (t))*HID)
        // lin_src per edge type: xs = x_src @ Wsrc + bsrc
        tile_gemm<<<GB, 256, SMEM_TOTAL>>>(xb, WOFF(Wsrc,0), BOFF(bsrc,0), nullptr, nullptr, nullptr, xs_bb, NB, nullptr, 0);
        tile_gemm<<<GB, 256, SMEM_TOTAL>>>(xb, WOFF(Wsrc,1), BOFF(bsrc,1), nullptr, nullptr, nullptr, xs_bc, NB, nullptr, 0);
        tile_gemm<<<GC, 256, SMEM_TOTAL>>>(xc, WOFF(Wsrc,2), BOFF(bsrc,2), nullptr, nullptr, nullptr, xs_cc, NC, nullptr, 0);
        tile_gemm<<<GC, 256, SMEM_TOTAL>>>(xc, WOFF(Wsrc,3), BOFF(bsrc,3), nullptr, nullptr, nullptr, xs_cb, NC, nullptr, 0);
        // agg init: ((1+eps)*x_dst) @ Wdst + bdst
        tile_gemm<<<GB, 256, SMEM_TOTAL>>>(xb, WOFF(Wdst,0), BOFF(bdst,0), nullptr, nullptr, nullptr, agg_bb, NB, eps + l*4 + 0, 0);
        tile_gemm<<<GB, 256, SMEM_TOTAL>>>(xb, WOFF(Wdst,3), BOFF(bdst,3), nullptr, nullptr, nullptr, agg_cb, NB, eps + l*4 + 3, 0);
        tile_gemm<<<GC, 256, SMEM_TOTAL>>>(xc, WOFF(Wdst,1), BOFF(bdst,1), nullptr, nullptr, nullptr, agg_bc, NC, eps + l*4 + 1, 0);
        tile_gemm<<<GC, 256, SMEM_TOTAL>>>(xc, WOFF(Wdst,2), BOFF(bdst,2), nullptr, nullptr, nullptr, agg_cc, NC, eps + l*4 + 2, 0);
        // fused edge encode + message + scatter
        {
            const float* XSs[4]  = {xs_bb, xs_bc, xs_cc, xs_cb};
            float*       AGGs[4] = {agg_bb, agg_bc, agg_cc, agg_cb};
            for (int tt = 0; tt < 4; tt++){
                int E = in_sizes[4 + 3*tt];
                tile_gemm<<<(E + 127)/128, 256, SMEM_TOTAL>>>(ea[tt], WOFF(We,tt), BOFF(be,tt),
                                                              ei[tt], ewt[tt], XSs[tt], AGGs[tt], E, nullptr, 0);
            }
        }
        // MLP layer 1 (gelu)
        tile_gemm<<<GB, 256, SMEM_TOTAL>>>(agg_bb, WOFF(Wm1,0), BOFF(bm1,0), nullptr, nullptr, nullptr, xs_bb, NB, nullptr, 1);
        tile_gemm<<<GB, 256, SMEM_TOTAL>>>(agg_cb, WOFF(Wm1,3), BOFF(bm1,3), nullptr, nullptr, nullptr, xs_bc, NB, nullptr, 1);
        tile_gemm<<<GC, 256, SMEM_TOTAL>>>(agg_bc, WOFF(Wm1,1), BOFF(bm1,1), nullptr, nullptr, nullptr, xs_cc, NC, nullptr, 1);
        tile_gemm<<<GC, 256, SMEM_TOTAL>>>(agg_cc, WOFF(Wm1,2), BOFF(bm1,2), nullptr, nullptr, nullptr, xs_cb, NC, nullptr, 1);
        // MLP layer 2
        tile_gemm<<<GB, 256, SMEM_TOTAL>>>(xs_bb, WOFF(Wm2,0), BOFF(bm2,0), nullptr, nullptr, nullptr, agg_bb, NB, nullptr, 0);
        tile_gemm<<<GB, 256, SMEM_TOTAL>>>(xs_bc, WOFF(Wm2,3), BOFF(bm2,3), nullptr, nullptr, nullptr, agg_cb, NB, nullptr, 0);
        tile_gemm<<<GC, 256, SMEM_TOTAL>>>(xs_cc, WOFF(Wm2,1), BOFF(bm2,1), nullptr, nullptr, nullptr, agg_bc, NC, nullptr, 0);
        tile_gemm<<<GC, 256, SMEM_TOTAL>>>(xs_cb, WOFF(Wm2,2), BOFF(bm2,2), nullptr, nullptr, nullptr, agg_cc, NC, nullptr, 0);
        // residual + gelu combine
        combine_kernel<<<(NBF+255)/256, 256>>>(xb, agg_bb, agg_cb, NBF);
        combine_kernel<<<(NCF+255)/256, 256>>>(xc, agg_bc, agg_cc, NCF);
        #undef WOFF
        #undef BOFF
    }

    float* out = (float*)d_out;
    cudaMemcpyAsync(out,       xb, sizeof(float)*(size_t)NBF, cudaMemcpyDeviceToDevice, 0);
    cudaMemcpyAsync(out + NBF, xc, sizeof(float)*(size_t)NCF, cudaMemcpyDeviceToDevice, 0);
}